// round 6
// baseline (speedup 1.0000x reference)
#include <cuda_runtime.h>
#include <cuda_bf16.h>
#include <cstdint>

#define THREADS  512
#define TILE     128
#define K1       160
#define N1       128
#define K2       128
#define N2       64
#define NODE_DIM 64
#define EDGE_DIM 32

#define AST   168   // A tile + W1T row stride in bf16 (336 B)
#define W2ST  136   // W2T row stride in bf16 (272 B)
#define PST   72    // partial C2 row stride in floats (conflict-free)

#define OFF_W1H  0
#define OFF_W1L  (OFF_W1H + N1*AST*2)          // 43008
#define OFF_W2H  (OFF_W1L + N1*AST*2)          // 86016
#define OFF_W2L  (OFF_W2H + N2*W2ST*2)         // 103424
#define OFF_AH   (OFF_W2L + N2*W2ST*2)         // 120832
#define OFF_AL   (OFF_AH + TILE*AST*2)         // 163840
#define OFF_B1   (OFF_AL + TILE*AST*2)         // 206848
#define OFF_B2   (OFF_B1 + N1*4)
#define OFF_IS64 (OFF_B2 + N2*4)
#define SMEM_TOTAL (OFF_IS64 + 64)
// partial C2 buffer overlays A-hi region (A fully consumed before stores)
#define OFF_P    OFF_AH

__device__ __forceinline__ uint32_t s2u(const void* p){
    uint32_t a;
    asm("{ .reg .u64 t; cvta.to.shared.u64 t, %1; cvt.u32.u64 %0, t; }" : "=r"(a) : "l"(p));
    return a;
}
__device__ __forceinline__ void ldsm4(uint32_t& r0, uint32_t& r1, uint32_t& r2, uint32_t& r3,
                                      uint32_t addr){
    asm volatile("ldmatrix.sync.aligned.m8n8.x4.shared.b16 {%0,%1,%2,%3}, [%4];"
                 : "=r"(r0), "=r"(r1), "=r"(r2), "=r"(r3) : "r"(addr));
}
__device__ __forceinline__ void mma16816(float* c,
                                         uint32_t a0, uint32_t a1, uint32_t a2, uint32_t a3,
                                         uint32_t b0, uint32_t b1){
    asm volatile("mma.sync.aligned.m16n8k16.row.col.f32.bf16.bf16.f32 "
                 "{%0,%1,%2,%3}, {%4,%5,%6,%7}, {%8,%9}, {%0,%1,%2,%3};"
                 : "+f"(c[0]), "+f"(c[1]), "+f"(c[2]), "+f"(c[3])
                 : "r"(a0), "r"(a1), "r"(a2), "r"(a3), "r"(b0), "r"(b1));
}
__device__ __forceinline__ uint32_t packbf2(float a, float b){
    __nv_bfloat162 t = __float22bfloat162_rn(make_float2(a, b));
    return *reinterpret_cast<uint32_t*>(&t);
}
__device__ __forceinline__ float2 unpackbf2(uint32_t u){
    __nv_bfloat162 t = *reinterpret_cast<__nv_bfloat162*>(&u);
    return __bfloat1622float2(t);
}
__device__ __forceinline__ void split2(float a, float b, uint32_t& hi, uint32_t& lo){
    hi = packbf2(a, b);
    float2 f = unpackbf2(hi);
    lo = packbf2(a - f.x, b - f.y);
}

__global__ __launch_bounds__(THREADS, 1)
void edge_mlp_hmma(const float* __restrict__ x,
                   const float* __restrict__ edge_attr,
                   const float* __restrict__ W1,
                   const float* __restrict__ b1,
                   const float* __restrict__ W2,
                   const float* __restrict__ b2,
                   const void*  __restrict__ edge_index,
                   float* __restrict__ out,
                   int n_edges, int n_nodes)
{
    extern __shared__ __align__(128) char sm[];
    const uint32_t smb = s2u(sm);
    const int tid = threadIdx.x;
    const int wid = tid >> 5;
    const int lid = tid & 31;
    const int wrow = wid >> 1;     // 0..7: 16-edge row group
    const int wcol = wid & 1;      // 0..1: 64-col half of hidden dim

    float* b1s = (float*)(sm + OFF_B1);
    float* b2s = (float*)(sm + OFF_B2);

    if (tid == 0) {
        const long long* e64 = (const long long*)edge_index;
        int ok = 1;
        #pragma unroll 1
        for (int i = 0; i < 32; i++) {
            long long v = e64[i];
            if (v < 0 || v >= (long long)n_nodes) ok = 0;
        }
        *(int*)(sm + OFF_IS64) = ok;
    }

    // ---- weights: transpose to [n][k], bf16 hi/lo split ----
    for (int i = tid; i < K1 * N1; i += THREADS) {
        int k = i >> 7, n = i & 127;
        float w = W1[i];
        __nv_bfloat16 hb = __float2bfloat16(w);
        __nv_bfloat16 lb = __float2bfloat16(w - __bfloat162float(hb));
        int off = n * AST + k;
        *((__nv_bfloat16*)(sm + OFF_W1H) + off) = hb;
        *((__nv_bfloat16*)(sm + OFF_W1L) + off) = lb;
    }
    for (int i = tid; i < K2 * N2; i += THREADS) {
        int k = i >> 6, n = i & 63;
        float w = W2[i];
        __nv_bfloat16 hb = __float2bfloat16(w);
        __nv_bfloat16 lb = __float2bfloat16(w - __bfloat162float(hb));
        int off = n * W2ST + k;
        *((__nv_bfloat16*)(sm + OFF_W2H) + off) = hb;
        *((__nv_bfloat16*)(sm + OFF_W2L) + off) = lb;
    }
    if (tid < N1) b1s[tid] = b1[tid];
    if (tid < N2) b2s[tid] = b2[tid];
    __syncthreads();

    const int is64 = *(int*)(sm + OFF_IS64);
    const long long* idx64 = (const long long*)edge_index;
    const int*       idx32 = (const int*)edge_index;

    // gather: 4 threads per row, 10 float4 each
    const int grow = tid >> 2;
    const int gq   = tid & 3;

    // ldmatrix lane addressing
    const int lmrow = lid & 15;
    const int lmk   = (lid >> 4) << 3;
    const int bn    = ((lid >> 4) << 3) + (lid & 7);
    const int bk    = ((lid >> 3) & 1) << 3;

    const uint32_t aAH = smb + OFF_AH + (uint32_t)((wrow * 16 + lmrow) * AST + lmk) * 2;
    const uint32_t aAL = smb + OFF_AL + (uint32_t)((wrow * 16 + lmrow) * AST + lmk) * 2;
    const uint32_t aW1H = smb + OFF_W1H + (uint32_t)((wcol * 64 + bn) * AST + bk) * 2;
    const uint32_t aW1L = smb + OFF_W1L + (uint32_t)((wcol * 64 + bn) * AST + bk) * 2;
    const uint32_t aW2H = smb + OFF_W2H + (uint32_t)(bn * W2ST + wcol * 64 + bk) * 2;
    const uint32_t aW2L = smb + OFF_W2L + (uint32_t)(bn * W2ST + wcol * 64 + bk) * 2;

    const int q2 = (lid & 3) << 1;
    const int prow = lid >> 2;                  // 0..7
    float* Ppart = (float*)(sm + OFF_P) + wrow * (16 * PST);

    const int n_tiles = (n_edges + TILE - 1) / TILE;
    for (int tile = blockIdx.x; tile < n_tiles; tile += gridDim.x) {
        const int e_base = tile * TILE;

        // ================= gather -> A hi/lo bf16 =================
        {
            const int ge = e_base + grow;
            const float* xs = x;
            const float* xt = x;
            const float* ea = edge_attr;
            bool valid = (ge < n_edges);
            if (valid) {
                long long s, t;
                if (is64) { s = idx64[ge]; t = idx64[ge + n_edges]; }
                else      { s = idx32[ge]; t = idx32[ge + n_edges]; }
                xs = x + s * NODE_DIM;
                xt = x + t * NODE_DIM;
                ea = edge_attr + (long long)ge * EDGE_DIM;
            }
            char* rowH = sm + OFF_AH + grow * AST * 2;
            char* rowL = sm + OFF_AL + grow * AST * 2;
            #pragma unroll
            for (int j = 0; j < 10; j++) {
                const int col = (gq * 10 + j) * 4;
                float4 v = make_float4(0.f, 0.f, 0.f, 0.f);
                if (valid) {
                    if (col < 64)       v = *(const float4*)(xs + col);
                    else if (col < 128) v = *(const float4*)(xt + (col - 64));
                    else                v = *(const float4*)(ea + (col - 128));
                }
                uint32_t h01, l01, h23, l23;
                split2(v.x, v.y, h01, l01);
                split2(v.z, v.w, h23, l23);
                *(uint2*)(rowH + col * 2) = make_uint2(h01, h23);
                *(uint2*)(rowL + col * 2) = make_uint2(l01, l23);
            }
        }
        __syncthreads();

        // ================= GEMM1: 16 rows x 64 cols per warp =================
        float C1[8][4];
        #pragma unroll
        for (int i = 0; i < 8; i++)
            #pragma unroll
            for (int j = 0; j < 4; j++) C1[i][j] = 0.f;

        #pragma unroll
        for (int k = 0; k < 10; k++) {
            uint32_t ah0, ah1, ah2, ah3, al0, al1, al2, al3;
            ldsm4(ah0, ah1, ah2, ah3, aAH + k * 32);
            ldsm4(al0, al1, al2, al3, aAL + k * 32);
            #pragma unroll
            for (int nt2 = 0; nt2 < 4; nt2++) {
                uint32_t bh0, bh1, bh2, bh3, bl0, bl1, bl2, bl3;
                const uint32_t boff = (uint32_t)(nt2 * 16 * AST) * 2 + k * 32;
                ldsm4(bh0, bh1, bh2, bh3, aW1H + boff);
                ldsm4(bl0, bl1, bl2, bl3, aW1L + boff);
                mma16816(C1[2*nt2],   ah0, ah1, ah2, ah3, bh0, bh1);
                mma16816(C1[2*nt2],   al0, al1, al2, al3, bh0, bh1);
                mma16816(C1[2*nt2],   ah0, ah1, ah2, ah3, bl0, bl1);
                mma16816(C1[2*nt2+1], ah0, ah1, ah2, ah3, bh2, bh3);
                mma16816(C1[2*nt2+1], al0, al1, al2, al3, bh2, bh3);
                mma16816(C1[2*nt2+1], ah0, ah1, ah2, ah3, bl2, bl3);
            }
        }
        __syncthreads();   // all A reads done (partial buffer overlays A-hi)

        // ================= epilogue1 (regs) + GEMM2 partial over this k-half =================
        float C2[8][4];
        #pragma unroll
        for (int i = 0; i < 8; i++)
            #pragma unroll
            for (int j = 0; j < 4; j++) C2[i][j] = 0.f;

        #pragma unroll
        for (int j = 0; j < 4; j++) {
            const int cb = wcol * 64 + 16 * j;
            const float2 bA = *(const float2*)(b1s + cb + q2);
            const float2 bB = *(const float2*)(b1s + cb + 8 + q2);
            float v00 = fmaxf(C1[2*j][0]   + bA.x, 0.f);
            float v01 = fmaxf(C1[2*j][1]   + bA.y, 0.f);
            float v02 = fmaxf(C1[2*j][2]   + bA.x, 0.f);
            float v03 = fmaxf(C1[2*j][3]   + bA.y, 0.f);
            float v10 = fmaxf(C1[2*j+1][0] + bB.x, 0.f);
            float v11 = fmaxf(C1[2*j+1][1] + bB.y, 0.f);
            float v12 = fmaxf(C1[2*j+1][2] + bB.x, 0.f);
            float v13 = fmaxf(C1[2*j+1][3] + bB.y, 0.f);
            uint32_t ah0, al0, ah1, al1, ah2, al2, ah3, al3;
            split2(v00, v01, ah0, al0);
            split2(v02, v03, ah1, al1);
            split2(v10, v11, ah2, al2);
            split2(v12, v13, ah3, al3);

            #pragma unroll
            for (int nt2 = 0; nt2 < 4; nt2++) {
                uint32_t bh0, bh1, bh2, bh3, bl0, bl1, bl2, bl3;
                const uint32_t boff = (uint32_t)(nt2 * 16 * W2ST) * 2 + j * 32;
                ldsm4(bh0, bh1, bh2, bh3, aW2H + boff);
                ldsm4(bl0, bl1, bl2, bl3, aW2L + boff);
                mma16816(C2[2*nt2],   ah0, ah1, ah2, ah3, bh0, bh1);
                mma16816(C2[2*nt2],   al0, al1, al2, al3, bh0, bh1);
                mma16816(C2[2*nt2],   ah0, ah1, ah2, ah3, bl0, bl1);
                mma16816(C2[2*nt2+1], ah0, ah1, ah2, ah3, bh2, bh3);
                mma16816(C2[2*nt2+1], al0, al1, al2, al3, bh2, bh3);
                mma16816(C2[2*nt2+1], ah0, ah1, ah2, ah3, bl2, bl3);
            }
        }

        // odd warp (wcol==1) stores its k-half partial
        if (wcol) {
            #pragma unroll
            for (int nt = 0; nt < 8; nt++) {
                const int c = nt * 8 + q2;
                *(float2*)(Ppart + prow * PST + c)       = make_float2(C2[nt][0], C2[nt][1]);
                *(float2*)(Ppart + (prow + 8) * PST + c) = make_float2(C2[nt][2], C2[nt][3]);
            }
        }
        __syncthreads();

        // even warp reduces, adds b2, stores to gmem
        if (!wcol) {
            const int r0 = e_base + wrow * 16 + prow;
            #pragma unroll
            for (int nt = 0; nt < 8; nt++) {
                const int c = nt * 8 + q2;
                const float2 bb = *(const float2*)(b2s + c);
                const float2 p0 = *(const float2*)(Ppart + prow * PST + c);
                const float2 p1 = *(const float2*)(Ppart + (prow + 8) * PST + c);
                if (r0 < n_edges) {
                    float2 o0 = make_float2(C2[nt][0] + p0.x + bb.x,
                                            C2[nt][1] + p0.y + bb.y);
                    *(float2*)(out + (size_t)r0 * N2 + c) = o0;
                }
                if (r0 + 8 < n_edges) {
                    float2 o1 = make_float2(C2[nt][2] + p1.x + bb.x,
                                            C2[nt][3] + p1.y + bb.y);
                    *(float2*)(out + (size_t)(r0 + 8) * N2 + c) = o1;
                }
            }
        }
        __syncthreads();   // partial reads done before next gather overwrites region
    }
}

extern "C" void kernel_launch(void* const* d_in, const int* in_sizes, int n_in,
                              void* d_out, int out_size)
{
    const float* x  = (const float*)d_in[0];
    const float* ea = (const float*)d_in[1];
    const float* W1 = (const float*)d_in[2];
    const float* b1 = (const float*)d_in[3];
    const float* W2 = (const float*)d_in[4];
    const float* b2 = (const float*)d_in[5];
    const void*  ei = (const void*)d_in[6];
    float* out = (float*)d_out;

    const int n_nodes = in_sizes[0] / NODE_DIM;
    const int n_edges = in_sizes[1] / EDGE_DIM;
    const int n_tiles = (n_edges + TILE - 1) / TILE;
    int grid = n_tiles < 148 ? n_tiles : 148;

    cudaFuncSetAttribute(edge_mlp_hmma,
                         cudaFuncAttributeMaxDynamicSharedMemorySize, SMEM_TOTAL);
    edge_mlp_hmma<<<grid, THREADS, SMEM_TOTAL>>>(
        x, ea, W1, b1, W2, b2, ei, out, n_edges, n_nodes);
}